// round 13
// baseline (speedup 1.0000x reference)
#include <cuda_runtime.h>
#include <cooperative_groups.h>
#include <cstdint>

namespace cg = cooperative_groups;

#define BATCH     8
#define NPTS      32768
#define CIN_DIM   128
#define MS        (NPTS / 4)          // 8192 samples
#define CLUSTER_X 8                   // CTAs per batch (one CGA cluster)
#define NTHREADS  256
#define NWARPS    (NTHREADS / 32)     // 8
#define PPT       (NPTS / (CLUSTER_X * NTHREADS))   // 16 points per thread

// scratch for sampled indices (device global: no allocation allowed)
__device__ int g_sample_idx[BATCH * MS];

__device__ __forceinline__ uint32_t smem_u32(const void* p) {
    return (uint32_t)__cvta_generic_to_shared(p);
}

__global__ void noop_kernel() {}   // ncu launch-index shim

__global__ void __cluster_dims__(CLUSTER_X, 1, 1) __launch_bounds__(NTHREADS, 1)
fps_kernel(const float* __restrict__ xyz)
{
    cg::cluster_group cluster = cg::this_cluster();
    const int rank  = blockIdx.x & (CLUSTER_X - 1);   // cluster cta rank
    const int batch = blockIdx.x / CLUSTER_X;
    const int tid   = threadIdx.x;
    const int warp  = tid >> 5;
    const int lane  = tid & 31;

    // cross-CTA exchange: ONE slot per source CTA, parity double-buffered
    __shared__ __align__(16) uint4              slot_c[2][CLUSTER_X];
    __shared__ __align__(8)  unsigned long long slot_k[2][CLUSTER_X];
    // in-CTA block stage: one slot per warp
    __shared__ __align__(16) uint4              wp_c[NWARPS];
    __shared__ __align__(8)  unsigned long long wp_k[NWARPS];
    __shared__ __align__(8)  unsigned long long mbar;   // 8 arrivals per phase

    if (tid == 0) {
        asm volatile("mbarrier.init.shared.b64 [%0], %1;"
                     :: "r"(smem_u32(&mbar)), "r"(CLUSTER_X) : "memory");
    }
    __syncthreads();
    cluster.sync();      // all CTAs' mbarrier init visible before any remote arrive

    const float* sx = xyz + (size_t)batch * 3 * NPTS;
    const float* sy = sx + NPTS;
    const float* sz = sy + NPTS;

    const int base = rank * (NTHREADS * PPT) + tid;   // g = base + k*NTHREADS

    float px[PPT], py[PPT], pz[PPT], dst[PPT];
#pragma unroll
    for (int k = 0; k < PPT; k++) {
        const int g = base + k * NTHREADS;
        px[k]  = sx[g];
        py[k]  = sy[g];
        pz[k]  = sz[g];
        dst[k] = 1e10f;
    }

    // initial farthest = point 0 (reference's deterministic seed)
    float cx = sx[0], cy = sy[0], cz = sz[0];
    int   fi = 0;

    const uint32_t mb_local = smem_u32(&mbar);

    for (int t = 0; t < MS; t++) {
        if (rank == 0 && tid == 0)
            g_sample_idx[batch * MS + t] = fi;
        if (t == MS - 1) break;                 // last fi already recorded

        // ---- distance update + per-thread argmax (first-max keeps lowest g) ----
        float bv, bx, by, bz;
        uint32_t bg;
        {
            const float dx = __fadd_rn(px[0], -cx);
            const float dy = __fadd_rn(py[0], -cy);
            const float dz = __fadd_rn(pz[0], -cz);
            const float d  = __fmaf_rn(dz, dz, __fmaf_rn(dx, dx, __fmul_rn(dy, dy)));
            const float nd = fminf(dst[0], d);
            dst[0] = nd;
            bv = nd; bg = (uint32_t)base; bx = px[0]; by = py[0]; bz = pz[0];
        }
#pragma unroll
        for (int k = 1; k < PPT; k++) {
            const float dx = __fadd_rn(px[k], -cx);
            const float dy = __fadd_rn(py[k], -cy);
            const float dz = __fadd_rn(pz[k], -cz);
            const float d  = __fmaf_rn(dz, dz, __fmaf_rn(dx, dx, __fmul_rn(dy, dy)));
            const float nd = fminf(dst[k], d);
            dst[k] = nd;
            const bool p = nd > bv;             // strict > keeps earliest (lowest g)
            bv = p ? nd : bv;
            bg = p ? (uint32_t)(base + k * NTHREADS) : bg;
            bx = p ? px[k] : bx;
            by = p ? py[k] : by;
            bz = p ? pz[k] : bz;
        }

        // ---- warp argmax via redux (value max, then min index among maxima) ----
        const uint32_t vb   = __float_as_uint(bv);          // >=0 -> u32-ordered
        const uint32_t wmax = __reduce_max_sync(0xffffffffu, vb);
        const bool     eq   = (vb == wmax);
        const uint32_t gmin = __reduce_min_sync(0xffffffffu, eq ? bg : 0xffffffffu);
        const bool     win  = eq && (bg == gmin);           // unique lane

        const uint32_t wl = __ffs(__ballot_sync(0xffffffffu, win)) - 1;
        const uint32_t xb = __shfl_sync(0xffffffffu, __float_as_uint(bx), wl);
        const uint32_t yb = __shfl_sync(0xffffffffu, __float_as_uint(by), wl);
        const uint32_t zb = __shfl_sync(0xffffffffu, __float_as_uint(bz), wl);

        // ---- block stage: one winner per warp into smem ----
        if (lane == 0) {
            wp_k[warp] = ((unsigned long long)wmax << 32) | (unsigned long long)gmin;
            wp_c[warp] = make_uint4(xb, yb, zb, 0u);
        }
        __syncthreads();

        const int par = t & 1;

        // ---- warp 0: block argmax, then ONE push per destination CTA ----
        if (warp == 0) {
            unsigned long long bk = (lane < NWARPS) ? wp_k[lane] : 0ULL;
            const uint32_t v = (uint32_t)(bk >> 32);
            const uint32_t g = (uint32_t)bk;
            const uint32_t bmax = __reduce_max_sync(0xffffffffu, v);
            const bool     beq  = (lane < NWARPS) && (v == bmax);
            const uint32_t bfi  = __reduce_min_sync(0xffffffffu, beq ? g : 0xffffffffu);
            const bool     bwin = beq && (g == bfi);
            const uint32_t bl   = __ffs(__ballot_sync(0xffffffffu, bwin)) - 1;

            uint4 wc = (lane < NWARPS) ? wp_c[lane] : make_uint4(0u, 0u, 0u, 0u);
            const uint32_t cxb = __shfl_sync(0xffffffffu, wc.x, bl);
            const uint32_t cyb = __shfl_sync(0xffffffffu, wc.y, bl);
            const uint32_t czb = __shfl_sync(0xffffffffu, wc.z, bl);

            const unsigned long long key =
                ((unsigned long long)bmax << 32) | (unsigned long long)bfi;

            if (lane < CLUSTER_X) {   // lane r -> rank r, slot index = MY rank
                const uint32_t lc = smem_u32(&slot_c[par][rank]);
                const uint32_t lk = smem_u32(&slot_k[par][rank]);
                uint32_t rc, rk, rb;
                asm volatile("mapa.shared::cluster.u32 %0, %1, %2;" : "=r"(rc) : "r"(lc), "r"(lane));
                asm volatile("mapa.shared::cluster.u32 %0, %1, %2;" : "=r"(rk) : "r"(lk), "r"(lane));
                asm volatile("mapa.shared::cluster.u32 %0, %1, %2;" : "=r"(rb) : "r"(mb_local), "r"(lane));
                const unsigned long long xy =
                    ((unsigned long long)cyb << 32) | (unsigned long long)cxb;
                asm volatile("st.shared::cluster.b64 [%0], %1;" :: "r"(rc), "l"(xy) : "memory");
                asm volatile("st.shared::cluster.b32 [%0], %1;" :: "r"(rc + 8), "r"(czb) : "memory");
                asm volatile("st.shared::cluster.b64 [%0], %1;" :: "r"(rk), "l"(key) : "memory");
                asm volatile("mbarrier.arrive.release.cluster.shared::cluster.b64 _, [%0];"
                             :: "r"(rb) : "memory");
            }
        }

        // ---- consume: HW-sleep wait (8 arrivals), then plain LDS over 8 keys ----
        {
            uint32_t done;
            asm volatile(
                "{\n\t"
                ".reg .pred p;\n\t"
                "mbarrier.try_wait.parity.acquire.cluster.shared::cta.b64 p, [%1], %2;\n\t"
                "selp.b32 %0, 1, 0, p;\n\t"
                "}"
                : "=r"(done) : "r"(mb_local), "r"((uint32_t)par) : "memory");
            if (!done) {
                asm volatile(
                    "{\n\t"
                    ".reg .pred P1;\n\t"
                    "WAIT_LOOP_%=:\n\t"
                    "mbarrier.try_wait.parity.acquire.cluster.shared::cta.b64 P1, [%0], %1, 0x989680;\n\t"
                    "@P1 bra.uni WAIT_DONE_%=;\n\t"
                    "bra.uni WAIT_LOOP_%=;\n\t"
                    "WAIT_DONE_%=:\n\t"
                    "}"
                    :: "r"(mb_local), "r"((uint32_t)par) : "memory");
            }
        }

        const unsigned long long ck = (lane < CLUSTER_X) ? slot_k[par][lane] : 0ULL;
        const uint32_t vm = (uint32_t)(ck >> 32);
        const uint32_t gm = (uint32_t)ck;
        const uint32_t cmax = __reduce_max_sync(0xffffffffu, vm);
        const uint32_t cfi  = __reduce_min_sync(0xffffffffu,
                               ((lane < CLUSTER_X) && (vm == cmax)) ? gm : 0xffffffffu);

        // winner coords: local read from the producing CTA's slot (rank = g>>12)
        const uint4 c = slot_c[par][cfi >> 12];
        cx = __uint_as_float(c.x);
        cy = __uint_as_float(c.y);
        cz = __uint_as_float(c.z);
        fi = (int)cfi;
    }

    // exit barrier: keep cluster alive until peers consumed all pushes
    cluster.sync();
}

// Gather epilogue: out = [xyz_sampled (B,3,M) | feature_sampled (B,CIN,M)]
__global__ void gather_kernel(const float* __restrict__ xyz,
                              const float* __restrict__ feat,
                              float* __restrict__ out)
{
    const int m = blockIdx.x * blockDim.x + threadIdx.x;   // 0..MS-1
    const int b = blockIdx.y;
    if (m >= MS) return;

    const int i = g_sample_idx[b * MS + m];

    const float* sxyz = xyz + (size_t)b * 3 * NPTS;
    float*       oxyz = out + (size_t)b * 3 * MS;
#pragma unroll
    for (int c = 0; c < 3; c++)
        oxyz[(size_t)c * MS + m] = sxyz[(size_t)c * NPTS + i];

    const float* sf = feat + (size_t)b * CIN_DIM * NPTS;
    float*       of = out + (size_t)BATCH * 3 * MS + (size_t)b * CIN_DIM * MS;
#pragma unroll 8
    for (int c = 0; c < CIN_DIM; c++)
        of[(size_t)c * MS + m] = sf[(size_t)c * NPTS + i];
}

extern "C" void kernel_launch(void* const* d_in, const int* in_sizes, int n_in,
                              void* d_out, int out_size)
{
    const float* xyz  = (const float*)d_in[0];   // [B,3,N] fp32
    const float* feat = (const float*)d_in[1];   // [B,CIN,N] fp32
    float*       out  = (float*)d_out;

    // 4 no-op launches: probe ncu -s 5 indexing so fps_kernel gets captured
    for (int i = 0; i < 4; i++) noop_kernel<<<1, 1>>>();

    fps_kernel<<<BATCH * CLUSTER_X, NTHREADS>>>(xyz);

    dim3 grid((MS + 255) / 256, BATCH);
    gather_kernel<<<grid, 256>>>(xyz, feat, out);
}

// round 14
// speedup vs baseline: 1.1481x; 1.1481x over previous
#include <cuda_runtime.h>
#include <cooperative_groups.h>
#include <cstdint>

namespace cg = cooperative_groups;

#define BATCH     8
#define NPTS      32768
#define CIN_DIM   128
#define MS        (NPTS / 4)          // 8192 samples
#define CLUSTER_X 8                   // CTAs per batch (one CGA cluster)
#define NTHREADS  256
#define NWARPS    (NTHREADS / 32)     // 8
#define PPT       (NPTS / (CLUSTER_X * NTHREADS))   // 16 points per thread
#define NGRP      (PPT / 2)                          // 8 packed pairs
#define NSLOTS    (CLUSTER_X * NWARPS)               // 64 producer slots

// scratch for sampled indices (device global: no allocation allowed)
__device__ int g_sample_idx[BATCH * MS];

typedef unsigned long long ull;

__device__ __forceinline__ uint32_t smem_u32(const void* p) {
    return (uint32_t)__cvta_generic_to_shared(p);
}
__device__ __forceinline__ ull f2pack(float lo, float hi) {
    ull r; asm("mov.b64 %0, {%1, %2};" : "=l"(r) : "f"(lo), "f"(hi)); return r;
}
__device__ __forceinline__ void f2unpack(ull v, float& lo, float& hi) {
    asm("mov.b64 {%0, %1}, %2;" : "=f"(lo), "=f"(hi) : "l"(v));
}
__device__ __forceinline__ ull f2add(ull a, ull b) {
    ull r; asm("add.rn.f32x2 %0, %1, %2;" : "=l"(r) : "l"(a), "l"(b)); return r;
}
__device__ __forceinline__ ull f2mul(ull a, ull b) {
    ull r; asm("mul.rn.f32x2 %0, %1, %2;" : "=l"(r) : "l"(a), "l"(b)); return r;
}
__device__ __forceinline__ ull f2fma(ull a, ull b, ull c) {
    ull r; asm("fma.rn.f32x2 %0, %1, %2, %3;" : "=l"(r) : "l"(a), "l"(b), "l"(c)); return r;
}

__global__ void __cluster_dims__(CLUSTER_X, 1, 1) __launch_bounds__(NTHREADS, 1)
fps_kernel(const float* __restrict__ xyz)
{
    cg::cluster_group cluster = cg::this_cluster();
    const int rank  = blockIdx.x & (CLUSTER_X - 1);   // cluster cta rank
    const int batch = blockIdx.x / CLUSTER_X;
    const int tid   = threadIdx.x;
    const int warp  = tid >> 5;
    const int lane  = tid & 31;

    // exchange slots: [parity][slot] ; coords (x,y,z,pad) + key (u64: vbits<<32 | g)
    __shared__ __align__(16) uint4 slot_c[2][NSLOTS];
    __shared__ __align__(8)  ull   slot_k[2][NSLOTS];
    __shared__ __align__(8)  ull   mbar;              // 64 arrivals per phase

    if (tid == 0) {
        asm volatile("mbarrier.init.shared.b64 [%0], %1;"
                     :: "r"(smem_u32(&mbar)), "r"(NSLOTS) : "memory");
    }
    __syncthreads();
    cluster.sync();      // all CTAs' mbarrier init visible before any remote arrive

    const float* sx = xyz + (size_t)batch * 3 * NPTS;
    const float* sy = sx + NPTS;
    const float* sz = sy + NPTS;

    const int base = rank * (NTHREADS * PPT) + tid;   // g = base + k*NTHREADS

    // register-resident packed point data (pair j = points k=2j, 2j+1)
    ull px2[NGRP], py2[NGRP], pz2[NGRP];
    float dst[PPT];
#pragma unroll
    for (int j = 0; j < NGRP; j++) {
        const int g0 = base + (2 * j) * NTHREADS;
        const int g1 = g0 + NTHREADS;
        px2[j] = f2pack(sx[g0], sx[g1]);
        py2[j] = f2pack(sy[g0], sy[g1]);
        pz2[j] = f2pack(sz[g0], sz[g1]);
    }
#pragma unroll
    for (int k = 0; k < PPT; k++) dst[k] = 1e10f;

    // initial farthest = point 0 (reference's deterministic seed)
    float cx = sx[0], cy = sy[0], cz = sz[0];
    int   fi = 0;

    // hoist remote address computations (loop-invariant): lane r -> rank r
    const int myslot = rank * NWARPS + warp;
    const uint32_t mb_local = smem_u32(&mbar);
    uint32_t rc0 = 0, rc1 = 0, rk0 = 0, rk1 = 0, rb = 0;
    if (lane < CLUSTER_X) {
        const uint32_t lc0 = smem_u32(&slot_c[0][myslot]);
        const uint32_t lc1 = smem_u32(&slot_c[1][myslot]);
        const uint32_t lk0 = smem_u32(&slot_k[0][myslot]);
        const uint32_t lk1 = smem_u32(&slot_k[1][myslot]);
        asm volatile("mapa.shared::cluster.u32 %0, %1, %2;" : "=r"(rc0) : "r"(lc0), "r"(lane));
        asm volatile("mapa.shared::cluster.u32 %0, %1, %2;" : "=r"(rc1) : "r"(lc1), "r"(lane));
        asm volatile("mapa.shared::cluster.u32 %0, %1, %2;" : "=r"(rk0) : "r"(lk0), "r"(lane));
        asm volatile("mapa.shared::cluster.u32 %0, %1, %2;" : "=r"(rk1) : "r"(lk1), "r"(lane));
        asm volatile("mapa.shared::cluster.u32 %0, %1, %2;" : "=r"(rb)  : "r"(mb_local), "r"(lane));
    }

    for (int t = 0; t < MS; t++) {
        if (rank == 0 && tid == 0)
            g_sample_idx[batch * MS + t] = fi;
        if (t == MS - 1) break;                 // last fi already recorded

        // ---- packed distance update (no inline tracking) ----
        // scalar-identical rounding: d = fma(dz,dz, fma(dx,dx, dy*dy))
        const ull ncx2 = f2pack(-cx, -cx);
        const ull ncy2 = f2pack(-cy, -cy);
        const ull ncz2 = f2pack(-cz, -cz);
#pragma unroll
        for (int j = 0; j < NGRP; j++) {
            const ull dxp = f2add(px2[j], ncx2);
            const ull dyp = f2add(py2[j], ncy2);
            const ull dzp = f2add(pz2[j], ncz2);
            const ull dp  = f2fma(dzp, dzp, f2fma(dxp, dxp, f2mul(dyp, dyp)));
            float d0, d1;
            f2unpack(dp, d0, d1);
            dst[2 * j]     = fminf(dst[2 * j],     d0);
            dst[2 * j + 1] = fminf(dst[2 * j + 1], d1);
        }

        // ---- value max: 4-level tree over 16 dst ----
        float m0 = fmaxf(dst[0],  dst[1]);
        float m1 = fmaxf(dst[2],  dst[3]);
        float m2 = fmaxf(dst[4],  dst[5]);
        float m3 = fmaxf(dst[6],  dst[7]);
        float m4 = fmaxf(dst[8],  dst[9]);
        float m5 = fmaxf(dst[10], dst[11]);
        float m6 = fmaxf(dst[12], dst[13]);
        float m7 = fmaxf(dst[14], dst[15]);
        m0 = fmaxf(m0, m1); m2 = fmaxf(m2, m3);
        m4 = fmaxf(m4, m5); m6 = fmaxf(m6, m7);
        m0 = fmaxf(m0, m2); m4 = fmaxf(m4, m6);
        const float bv = fmaxf(m0, m4);

        // ---- warp value max via redux (>=0 floats: u32-ordered) ----
        const uint32_t vb   = __float_as_uint(bv);
        const uint32_t wmax = __reduce_max_sync(0xffffffffu, vb);

        // ---- index extraction: lowest k with dst[k]==wmax (bit compare) ----
        int lk = PPT;
#pragma unroll
        for (int k = PPT - 1; k >= 0; k--)
            lk = (__float_as_uint(dst[k]) == wmax) ? k : lk;
        const uint32_t bg = (lk < PPT) ? (uint32_t)(base + lk * NTHREADS) : 0xffffffffu;

        const uint32_t gmin = __reduce_min_sync(0xffffffffu, bg);
        const bool     win  = (bg == gmin) && (lk < PPT);     // unique lane
        const uint32_t wl   = __ffs(__ballot_sync(0xffffffffu, win)) - 1;

        // winner coords: single-lane global fetch (own shard: L1-resident)
        float wx = 0.f, wy = 0.f, wz = 0.f;
        if (win) { wx = sx[bg]; wy = sy[bg]; wz = sz[bg]; }
        const uint32_t xb = __shfl_sync(0xffffffffu, __float_as_uint(wx), wl);
        const uint32_t yb = __shfl_sync(0xffffffffu, __float_as_uint(wy), wl);
        const uint32_t zb = __shfl_sync(0xffffffffu, __float_as_uint(wz), wl);

        const int par = t & 1;
        const ull key = ((ull)wmax << 32) | (ull)gmin;

        // ---- push to all 8 CTAs (lane r -> rank r): weak stores, release-arrive ----
        if (lane < CLUSTER_X) {
            const uint32_t rc = par ? rc1 : rc0;
            const uint32_t rk = par ? rk1 : rk0;
            const ull xy = ((ull)yb << 32) | (ull)xb;
            asm volatile("st.shared::cluster.b64 [%0], %1;" :: "r"(rc), "l"(xy) : "memory");
            asm volatile("st.shared::cluster.b32 [%0], %1;" :: "r"(rc + 8), "r"(zb) : "memory");
            asm volatile("st.shared::cluster.b64 [%0], %1;" :: "r"(rk), "l"(key) : "memory");
            asm volatile("mbarrier.arrive.release.cluster.shared::cluster.b64 _, [%0];"
                         :: "r"(rb) : "memory");
        }

        // ---- consume: HW-sleep wait (64 arrivals), then plain LDS reads ----
        {
            uint32_t done;
            asm volatile(
                "{\n\t"
                ".reg .pred p;\n\t"
                "mbarrier.try_wait.parity.acquire.cluster.shared::cta.b64 p, [%1], %2;\n\t"
                "selp.b32 %0, 1, 0, p;\n\t"
                "}"
                : "=r"(done) : "r"(mb_local), "r"((uint32_t)par) : "memory");
            if (!done) {
                asm volatile(
                    "{\n\t"
                    ".reg .pred P1;\n\t"
                    "WAIT_LOOP_%=:\n\t"
                    "mbarrier.try_wait.parity.acquire.cluster.shared::cta.b64 P1, [%0], %1, 0x989680;\n\t"
                    "@P1 bra.uni WAIT_DONE_%=;\n\t"
                    "bra.uni WAIT_LOOP_%=;\n\t"
                    "WAIT_DONE_%=:\n\t"
                    "}"
                    :: "r"(mb_local), "r"((uint32_t)par) : "memory");
            }
        }

        const ull k0 = slot_k[par][lane];
        const ull k1 = slot_k[par][lane + 32];
        const uint32_t v0 = (uint32_t)(k0 >> 32), g0 = (uint32_t)k0;
        const uint32_t v1 = (uint32_t)(k1 >> 32), g1 = (uint32_t)k1;
        const bool q  = (v0 > v1) || (v0 == v1 && g0 < g1);
        const uint32_t vm = q ? v0 : v1;
        const uint32_t gm = q ? g0 : g1;

        const uint32_t cmax = __reduce_max_sync(0xffffffffu, vm);
        const uint32_t cfi  = __reduce_min_sync(0xffffffffu, (vm == cmax) ? gm : 0xffffffffu);

        // winner coords: local read from the producing warp's slot
        const int ws = ((int)(cfi >> 12) << 3) | (((int)cfi & 255) >> 5);
        const uint4 c = slot_c[par][ws];
        cx = __uint_as_float(c.x);
        cy = __uint_as_float(c.y);
        cz = __uint_as_float(c.z);
        fi = (int)cfi;
    }

    // exit barrier: keep cluster alive until peers consumed all pushes
    cluster.sync();
}

// Gather epilogue: out = [xyz_sampled (B,3,M) | feature_sampled (B,CIN,M)]
__global__ void gather_kernel(const float* __restrict__ xyz,
                              const float* __restrict__ feat,
                              float* __restrict__ out)
{
    const int m = blockIdx.x * blockDim.x + threadIdx.x;   // 0..MS-1
    const int b = blockIdx.y;
    if (m >= MS) return;

    const int i = g_sample_idx[b * MS + m];

    const float* sxyz = xyz + (size_t)b * 3 * NPTS;
    float*       oxyz = out + (size_t)b * 3 * MS;
#pragma unroll
    for (int c = 0; c < 3; c++)
        oxyz[(size_t)c * MS + m] = sxyz[(size_t)c * NPTS + i];

    const float* sf = feat + (size_t)b * CIN_DIM * NPTS;
    float*       of = out + (size_t)BATCH * 3 * MS + (size_t)b * CIN_DIM * MS;
#pragma unroll 8
    for (int c = 0; c < CIN_DIM; c++)
        of[(size_t)c * MS + m] = sf[(size_t)c * NPTS + i];
}

extern "C" void kernel_launch(void* const* d_in, const int* in_sizes, int n_in,
                              void* d_out, int out_size)
{
    const float* xyz  = (const float*)d_in[0];   // [B,3,N] fp32
    const float* feat = (const float*)d_in[1];   // [B,CIN,N] fp32
    float*       out  = (float*)d_out;

    fps_kernel<<<BATCH * CLUSTER_X, NTHREADS>>>(xyz);

    dim3 grid((MS + 255) / 256, BATCH);
    gather_kernel<<<grid, 256>>>(xyz, feat, out);
}